// round 9
// baseline (speedup 1.0000x reference)
#include <cuda_runtime.h>
#include <cuda_fp16.h>

// Problem constants (fixed by reference)
#define VOCAB      32000
#define EMBED_DIM  128
#define BATCH      32
#define MAX_TREES  512
#define NSEG       (BATCH * MAX_TREES)   // 16384

#define CONV_BLOCKS   4000               // blocks doing table conversion
#define BOUND_BLOCKS  65                 // blocks doing segment bounds (16385 threads)

// Scratch (allocation-free __device__ globals)
__device__ int g_seg_start[NSEG + 1];
// Packed interleaved fp16 tables: per token, 512B record =
//   [128 fp16 key row | 128 fp16 value row] = 32 uint4 (lane l owns uint4 l).
__device__ __align__(16) uint4 g_pack[VOCAB * 32];

// ---------------------------------------------------------------------------
// Kernel 0 (fused): blocks [0, CONV_BLOCKS) convert the f32 tables to the
// packed fp16 layout; blocks [CONV_BLOCKS, +BOUND_BLOCKS) binary-search the
// segment boundaries. Outputs are disjoint; both complete before kernel 2.
// ---------------------------------------------------------------------------
__global__ void __launch_bounds__(256)
prep_kernel(const float4* __restrict__ C_hop,
            const float4* __restrict__ C_hop1,
            const int*    __restrict__ tree_ids, int n) {
    if (blockIdx.x < CONV_BLOCKS) {
        const int NT = VOCAB * 32;                 // 1,024,000 output uint4s
        int j = blockIdx.x * blockDim.x + threadIdx.x;
        if (j >= NT) return;
        const int r = j >> 5;                      // token row
        const int c = j & 31;                      // uint4 slot in 512B record
        const float4* src = (c < 16) ? C_hop : C_hop1;
        const int cc = c & 15;

        float4 a0 = __ldg(&src[r * 32 + 2 * cc]);
        float4 a1 = __ldg(&src[r * 32 + 2 * cc + 1]);

        union { __half2 h2[4]; uint4 u; } p;
        p.h2[0] = __floats2half2_rn(a0.x, a0.y);
        p.h2[1] = __floats2half2_rn(a0.z, a0.w);
        p.h2[2] = __floats2half2_rn(a1.x, a1.y);
        p.h2[3] = __floats2half2_rn(a1.z, a1.w);
        g_pack[j] = p.u;
    } else {
        int s = (blockIdx.x - CONV_BLOCKS) * blockDim.x + threadIdx.x;
        if (s > NSEG) return;
        int lo = 0, hi = n;
        while (lo < hi) {
            int mid = (lo + hi) >> 1;
            if (__ldg(&tree_ids[mid]) < s) lo = mid + 1;
            else hi = mid;
        }
        g_seg_start[s] = lo;
    }
}

// ---------------------------------------------------------------------------
// Kernel 2: FOUR warps per segment (phase-strided over 32-token chunks),
// 2 segments per 256-thread block, smem combine. One 512B warp load per
// token fetches BOTH tables (lanes 0-15 key row, 16-31 value row).
// 65536 gathering warps x 4 loads in flight keeps the L2 queues full.
// ---------------------------------------------------------------------------
__device__ __forceinline__ void acc8(float4& sa, float4& sb, uint4 r) {
    union { uint4 u; __half2 h[4]; } c; c.u = r;
    float2 f;
    f = __half22float2(c.h[0]); sa.x += f.x; sa.y += f.y;
    f = __half22float2(c.h[1]); sa.z += f.x; sa.w += f.y;
    f = __half22float2(c.h[2]); sb.x += f.x; sb.y += f.y;
    f = __half22float2(c.h[3]); sb.z += f.x; sb.w += f.y;
}

__global__ void __launch_bounds__(256)
seg_sum_kernel(const int* __restrict__ token_ids,
               float4*    __restrict__ out)        // [2][NSEG][32] float4
{
    // smem partials: [2 segs][4 subwarps][32 lanes][2 float4]
    __shared__ float4 part[2][4][32][2];

    const int tid   = threadIdx.x;
    const int w     = tid >> 5;          // warp 0..7
    const int lane  = tid & 31;
    const int which = w >> 2;            // segment slot in block (0/1)
    const int sub   = w & 3;             // chunk phase 0..3

    const int seg = blockIdx.x * 2 + which;   // grid = NSEG/2
    const int beg = g_seg_start[seg];
    const int end = g_seg_start[seg + 1];
    const int len   = end - beg;
    const int nfull = len >> 5;          // full 32-token chunks
    const int rem   = len & 31;

    float4 s0a = make_float4(0.f,0.f,0.f,0.f), s0b = make_float4(0.f,0.f,0.f,0.f);
    float4 s1a = make_float4(0.f,0.f,0.f,0.f), s1b = make_float4(0.f,0.f,0.f,0.f);

    // Full chunks with index ≡ sub (mod 4)
    for (int c = sub; c < nfull; c += 4) {
        const int base = beg + (c << 5);
        const int myid = __ldg(&token_ids[base + lane]);
        #pragma unroll
        for (int u = 0; u < 32; u += 4) {
            int t0 = __shfl_sync(0xffffffffu, myid, u + 0);
            int t1 = __shfl_sync(0xffffffffu, myid, u + 1);
            int t2 = __shfl_sync(0xffffffffu, myid, u + 2);
            int t3 = __shfl_sync(0xffffffffu, myid, u + 3);
            uint4 r0 = __ldcg(&g_pack[t0 * 32 + lane]);
            uint4 r1 = __ldcg(&g_pack[t1 * 32 + lane]);
            uint4 r2 = __ldcg(&g_pack[t2 * 32 + lane]);
            uint4 r3 = __ldcg(&g_pack[t3 * 32 + lane]);
            acc8(s0a, s0b, r0);
            acc8(s1a, s1b, r1);
            acc8(s0a, s0b, r2);
            acc8(s1a, s1b, r3);
        }
    }
    // Partial chunk (index nfull) owned by the warp whose phase matches.
    if (rem && (nfull & 3) == sub) {
        const int base = beg + (nfull << 5);
        const int myid = (lane < rem) ? __ldg(&token_ids[base + lane]) : 0;
        for (int u = 0; u < rem; u++) {
            int t = __shfl_sync(0xffffffffu, myid, u);
            uint4 r = __ldcg(&g_pack[t * 32 + lane]);
            acc8(s0a, s0b, r);
        }
    }

    s0a.x += s1a.x; s0a.y += s1a.y; s0a.z += s1a.z; s0a.w += s1a.w;
    s0b.x += s1b.x; s0b.y += s1b.y; s0b.z += s1b.z; s0b.w += s1b.w;

    part[which][sub][lane][0] = s0a;
    part[which][sub][lane][1] = s0b;
    __syncthreads();

    // Warps 0 and 4 combine the 4 partials of their segment and write out.
    if (sub == 0) {
        float4 ca = part[which][0][lane][0];
        float4 cb = part[which][0][lane][1];
        #pragma unroll
        for (int s = 1; s < 4; s++) {
            float4 pa = part[which][s][lane][0];
            float4 pb = part[which][s][lane][1];
            ca.x += pa.x; ca.y += pa.y; ca.z += pa.z; ca.w += pa.w;
            cb.x += pb.x; cb.y += pb.y; cb.z += pb.z; cb.w += pb.w;
        }
        // lanes 0-15 hold key-row floats [8c..8c+8); lanes 16-31 value-row.
        const int tbl = lane >> 4;          // 0 = key, 1 = value
        const int col = lane & 15;
        float4* dst = &out[(((size_t)tbl * NSEG) + seg) * 32 + col * 2];
        dst[0] = ca;
        dst[1] = cb;
    }
}

// ---------------------------------------------------------------------------
// Launch
// ---------------------------------------------------------------------------
extern "C" void kernel_launch(void* const* d_in, const int* in_sizes, int n_in,
                              void* d_out, int out_size) {
    const int*    token_ids = (const int*)   d_in[0];
    const int*    tree_ids  = (const int*)   d_in[1];
    const float4* C_hop     = (const float4*)d_in[2];
    const float4* C_hop1    = (const float4*)d_in[3];
    float4*       out       = (float4*)      d_out;

    const int n = in_sizes[0];  // TOTAL_TOKENS

    // Kernel 0: fused table conversion + segment bounds
    prep_kernel<<<CONV_BLOCKS + BOUND_BLOCKS, 256>>>(C_hop, C_hop1, tree_ids, n);

    // Kernel 2: 4 warps/segment, 2 segments/block -> 8192 blocks
    seg_sum_kernel<<<NSEG / 2, 256>>>(token_ids, out);
}

// round 10
// speedup vs baseline: 1.0896x; 1.0896x over previous
#include <cuda_runtime.h>
#include <cuda_fp16.h>

// Problem constants (fixed by reference)
#define VOCAB      32000
#define EMBED_DIM  128
#define BATCH      32
#define MAX_TREES  512
#define NSEG       (BATCH * MAX_TREES)   // 16384

#define CONV_BLOCKS   4000               // blocks doing table conversion
#define BOUND_BLOCKS  65                 // blocks doing segment bounds

// Scratch (allocation-free __device__ globals)
__device__ int g_seg_start[NSEG + 1];
// Packed interleaved fp16 tables: per token, 512B record =
//   [128 fp16 key row | 128 fp16 value row] = 32 uint4 (lane l owns uint4 l).
// Row 0 (PAD token) is exactly zero -> safe padding target.
__device__ __align__(16) uint4 g_pack[VOCAB * 32];

// ---------------------------------------------------------------------------
// Kernel 0 (fused): blocks [0, CONV_BLOCKS) convert the f32 tables to the
// packed fp16 layout; remaining blocks binary-search segment boundaries.
// ---------------------------------------------------------------------------
__global__ void __launch_bounds__(256)
prep_kernel(const float4* __restrict__ C_hop,
            const float4* __restrict__ C_hop1,
            const int*    __restrict__ tree_ids, int n) {
    if (blockIdx.x < CONV_BLOCKS) {
        const int NT = VOCAB * 32;                 // 1,024,000 output uint4s
        int j = blockIdx.x * blockDim.x + threadIdx.x;
        if (j >= NT) return;
        const int r = j >> 5;                      // token row
        const int c = j & 31;                      // uint4 slot in 512B record
        const float4* src = (c < 16) ? C_hop : C_hop1;
        const int cc = c & 15;

        float4 a0 = __ldg(&src[r * 32 + 2 * cc]);
        float4 a1 = __ldg(&src[r * 32 + 2 * cc + 1]);

        union { __half2 h2[4]; uint4 u; } p;
        p.h2[0] = __floats2half2_rn(a0.x, a0.y);
        p.h2[1] = __floats2half2_rn(a0.z, a0.w);
        p.h2[2] = __floats2half2_rn(a1.x, a1.y);
        p.h2[3] = __floats2half2_rn(a1.z, a1.w);
        g_pack[j] = p.u;
    } else {
        int s = (blockIdx.x - CONV_BLOCKS) * blockDim.x + threadIdx.x;
        if (s > NSEG) return;
        int lo = 0, hi = n;
        while (lo < hi) {
            int mid = (lo + hi) >> 1;
            if (__ldg(&tree_ids[mid]) < s) lo = mid + 1;
            else hi = mid;
        }
        g_seg_start[s] = lo;
    }
}

// ---------------------------------------------------------------------------
// Helpers: packed f32x2 accumulate (Blackwell add.rn.f32x2) + fp16x8 adds
// ---------------------------------------------------------------------------
__device__ __forceinline__ void addf32x2(unsigned long long& a, float2 f) {
    unsigned long long b;
    asm("mov.b64 %0, {%1, %2};" : "=l"(b) : "f"(f.x), "f"(f.y));
    asm("add.rn.f32x2 %0, %0, %1;" : "+l"(a) : "l"(b));
}
__device__ __forceinline__ float2 u64_to_f2(unsigned long long a) {
    float2 f;
    asm("mov.b64 {%0, %1}, %2;" : "=f"(f.x), "=f"(f.y) : "l"(a));
    return f;
}
__device__ __forceinline__ uint4 hadd2x4(uint4 a, uint4 b) {
    union U { uint4 u; __half2 h[4]; };
    U x, y, r; x.u = a; y.u = b;
    r.h[0] = __hadd2(x.h[0], y.h[0]);
    r.h[1] = __hadd2(x.h[1], y.h[1]);
    r.h[2] = __hadd2(x.h[2], y.h[2]);
    r.h[3] = __hadd2(x.h[3], y.h[3]);
    return r.u;
}
__device__ __forceinline__ void flush_set(unsigned long long acc[4], uint4 s) {
    union { uint4 u; __half2 h[4]; } c; c.u = s;
    addf32x2(acc[0], __half22float2(c.h[0]));
    addf32x2(acc[1], __half22float2(c.h[1]));
    addf32x2(acc[2], __half22float2(c.h[2]));
    addf32x2(acc[3], __half22float2(c.h[3]));
}

// ---------------------------------------------------------------------------
// Kernel 2: TWO warps per segment (contiguous chunk split), 4 segments per
// 256-thread block, smem combine. One 512B warp load per token fetches BOTH
// tables. fp16 HADD2 partial sums (4 rotating sets, <=8 tokens each) are
// flushed to packed-f32x2 accumulators once per 32-token chunk: ~7 SASS
// insts per token-lane instead of ~20.
// ---------------------------------------------------------------------------
__global__ void __launch_bounds__(256)
seg_sum_kernel(const int* __restrict__ token_ids,
               float4*    __restrict__ out)        // [2][NSEG][32] float4
{
    __shared__ unsigned long long part[4][32][4];  // 4KB

    const int tid   = threadIdx.x;
    const int w     = tid >> 5;          // warp 0..7
    const int lane  = tid & 31;
    const int which = w >> 1;            // segment slot 0..3
    const int sub   = w & 1;             // half 0/1

    const int seg = blockIdx.x * 4 + which;        // grid = NSEG/4
    const int beg = g_seg_start[seg];
    const int end = g_seg_start[seg + 1];
    const int cnt = end - beg;

    const int T     = (cnt + 31) >> 5;   // total 32-token chunks
    const int nfull = cnt >> 5;          // full chunks
    const int split = (T + 1) >> 1;
    const int cbeg  = sub ? split : 0;
    const int cend  = sub ? T     : split;

    unsigned long long acc[4] = {0ull, 0ull, 0ull, 0ull};
    const uint4 z4 = make_uint4(0u, 0u, 0u, 0u);

    for (int c = cbeg; c < cend; c++) {
        const int base = beg + (c << 5);
        uint4 h0 = z4, h1 = z4, h2 = z4, h3 = z4;

        if (c < nfull) {
            const int myid = __ldg(&token_ids[base + lane]);
            #pragma unroll
            for (int u = 0; u < 32; u += 4) {
                int t0 = __shfl_sync(0xffffffffu, myid, u + 0);
                int t1 = __shfl_sync(0xffffffffu, myid, u + 1);
                int t2 = __shfl_sync(0xffffffffu, myid, u + 2);
                int t3 = __shfl_sync(0xffffffffu, myid, u + 3);
                uint4 r0 = __ldcg(&g_pack[t0 * 32 + lane]);
                uint4 r1 = __ldcg(&g_pack[t1 * 32 + lane]);
                uint4 r2 = __ldcg(&g_pack[t2 * 32 + lane]);
                uint4 r3 = __ldcg(&g_pack[t3 * 32 + lane]);
                h0 = hadd2x4(h0, r0);
                h1 = hadd2x4(h1, r1);
                h2 = hadd2x4(h2, r2);
                h3 = hadd2x4(h3, r3);
            }
        } else {
            // Partial chunk: pad to a multiple of 4 with token 0 (zero row).
            const int valid = end - base;            // 1..31
            const int myid  = (lane < valid) ? __ldg(&token_ids[base + lane]) : 0;
            const int lim   = (valid + 3) & ~3;
            for (int u = 0; u < lim; u += 4) {
                int t0 = __shfl_sync(0xffffffffu, myid, u + 0);
                int t1 = __shfl_sync(0xffffffffu, myid, u + 1);
                int t2 = __shfl_sync(0xffffffffu, myid, u + 2);
                int t3 = __shfl_sync(0xffffffffu, myid, u + 3);
                uint4 r0 = __ldcg(&g_pack[t0 * 32 + lane]);
                uint4 r1 = __ldcg(&g_pack[t1 * 32 + lane]);
                uint4 r2 = __ldcg(&g_pack[t2 * 32 + lane]);
                uint4 r3 = __ldcg(&g_pack[t3 * 32 + lane]);
                h0 = hadd2x4(h0, r0);
                h1 = hadd2x4(h1, r1);
                h2 = hadd2x4(h2, r2);
                h3 = hadd2x4(h3, r3);
            }
        }
        // Flush fp16 partial sums (each set held <=8 tokens) into f32x2.
        flush_set(acc, h0);
        flush_set(acc, h1);
        flush_set(acc, h2);
        flush_set(acc, h3);
    }

    // Combine the two warps of each segment via smem.
    if (sub == 1) {
        part[which][lane][0] = acc[0];
        part[which][lane][1] = acc[1];
        part[which][lane][2] = acc[2];
        part[which][lane][3] = acc[3];
    }
    __syncthreads();

    if (sub == 0) {
        float2 f0 = u64_to_f2(acc[0]), g0 = u64_to_f2(part[which][lane][0]);
        float2 f1 = u64_to_f2(acc[1]), g1 = u64_to_f2(part[which][lane][1]);
        float2 f2 = u64_to_f2(acc[2]), g2 = u64_to_f2(part[which][lane][2]);
        float2 f3 = u64_to_f2(acc[3]), g3 = u64_to_f2(part[which][lane][3]);

        float4 A = make_float4(f0.x + g0.x, f0.y + g0.y, f1.x + g1.x, f1.y + g1.y);
        float4 B = make_float4(f2.x + g2.x, f2.y + g2.y, f3.x + g3.x, f3.y + g3.y);

        // lanes 0-15: key row floats [8*lane, 8*lane+8); lanes 16-31: value.
        const int tbl = lane >> 4;
        const int col = lane & 15;
        float4* dst = &out[(((size_t)tbl * NSEG) + seg) * 32 + col * 2];
        dst[0] = A;
        dst[1] = B;
    }
}

// ---------------------------------------------------------------------------
// Launch
// ---------------------------------------------------------------------------
extern "C" void kernel_launch(void* const* d_in, const int* in_sizes, int n_in,
                              void* d_out, int out_size) {
    const int*    token_ids = (const int*)   d_in[0];
    const int*    tree_ids  = (const int*)   d_in[1];
    const float4* C_hop     = (const float4*)d_in[2];
    const float4* C_hop1    = (const float4*)d_in[3];
    float4*       out       = (float4*)      d_out;

    const int n = in_sizes[0];  // TOTAL_TOKENS

    // Kernel 0: fused table conversion + segment bounds
    prep_kernel<<<CONV_BLOCKS + BOUND_BLOCKS, 256>>>(C_hop, C_hop1, tree_ids, n);

    // Kernel 2: 2 warps/segment, 4 segments/block -> 4096 blocks
    seg_sum_kernel<<<NSEG / 4, 256>>>(token_ids, out);
}